// round 2
// baseline (speedup 1.0000x reference)
#include <cuda_runtime.h>

// LIF spike scan: x is [T=8, N] fp32, N = 32*128*32*32 = 4,194,304.
// Per element-column: mem = beta*mem + x[t]; spk = (mem >= 0.5); mem *= (1-spk).
// Output spikes, same shape as x.
//
// Strategy: pure streaming kernel. One thread owns 4 contiguous fp32 columns
// (float4). All 8 time-slice loads are independent addresses -> issue all 8
// LDG.128 up front (MLP=8), run the tiny serial recurrence in registers,
// then 8 STG.128. HBM-bound; everything else is noise.

#ifndef LIF_T
#define LIF_T 8
#endif

__global__ void __launch_bounds__(256, 8)
lif_spike_kernel(const float4* __restrict__ x, float4* __restrict__ out, int n4) {
    int i = blockIdx.x * blockDim.x + threadIdx.x;
    if (i >= n4) return;

    const float beta = 0.25f;
    const float thresh = 0.5f;

    // Front-batched loads: 8 independent LDG.128
    float4 xt[LIF_T];
#pragma unroll
    for (int t = 0; t < LIF_T; ++t) {
        xt[t] = x[(size_t)t * n4 + i];
    }

    float4 sp[LIF_T];
    float m0 = 0.f, m1 = 0.f, m2 = 0.f, m3 = 0.f;
#pragma unroll
    for (int t = 0; t < LIF_T; ++t) {
        m0 = fmaf(beta, m0, xt[t].x);
        m1 = fmaf(beta, m1, xt[t].y);
        m2 = fmaf(beta, m2, xt[t].z);
        m3 = fmaf(beta, m3, xt[t].w);
        float s0 = (m0 >= thresh) ? 1.f : 0.f;
        float s1 = (m1 >= thresh) ? 1.f : 0.f;
        float s2 = (m2 >= thresh) ? 1.f : 0.f;
        float s3 = (m3 >= thresh) ? 1.f : 0.f;
        // hard reset: mem *= (1 - s)  ==  mem = s ? 0 : mem
        m0 = (s0 != 0.f) ? 0.f : m0;
        m1 = (s1 != 0.f) ? 0.f : m1;
        m2 = (s2 != 0.f) ? 0.f : m2;
        m3 = (s3 != 0.f) ? 0.f : m3;
        sp[t] = make_float4(s0, s1, s2, s3);
    }

#pragma unroll
    for (int t = 0; t < LIF_T; ++t) {
        out[(size_t)t * n4 + i] = sp[t];
    }
}

extern "C" void kernel_launch(void* const* d_in, const int* in_sizes, int n_in,
                              void* d_out, int out_size) {
    const float* x = (const float*)d_in[0];
    float* out = (float*)d_out;

    // x is [8, 32, 128, 32, 32] -> T=8, N = total/8
    int total = in_sizes[0];
    int T = LIF_T;
    int N = total / T;          // 4,194,304
    int n4 = N / 4;             // 1,048,576 float4 columns

    int threads = 256;
    int blocks = (n4 + threads - 1) / threads;  // 4096
    lif_spike_kernel<<<blocks, threads>>>((const float4*)x, (float4*)out, n4);
}

// round 4
// speedup vs baseline: 1.0021x; 1.0021x over previous
#include <cuda_runtime.h>

// LIF spike scan: x is [T=8, N] fp32, N = 32*128*32*32 = 4,194,304.
// Per column: mem = beta*mem + x[t]; spk = (mem >= 0.5); mem = spk ? 0 : mem.
//
// R2 change: output stores use streaming (evict-first) policy so the
// write-once spike tensor does not evict x from L2. x (~134MB) ~ L2 (~126MB),
// so across graph replays most of x stays L2-resident -> DRAM reads mostly
// disappear; kernel becomes DRAM-write + L2-read bound.

#ifndef LIF_T
#define LIF_T 8
#endif

__global__ void __launch_bounds__(256, 8)
lif_spike_kernel(const float4* __restrict__ x, float4* __restrict__ out, int n4) {
    int i = blockIdx.x * blockDim.x + threadIdx.x;
    if (i >= n4) return;

    const float beta = 0.25f;
    const float thresh = 0.5f;

    // Front-batched loads: 8 independent LDG.128 (default policy: DO cache in L2)
    float4 xt[LIF_T];
#pragma unroll
    for (int t = 0; t < LIF_T; ++t) {
        xt[t] = __ldg(&x[(size_t)t * n4 + i]);
    }

    float4 sp[LIF_T];
    float m0 = 0.f, m1 = 0.f, m2 = 0.f, m3 = 0.f;
#pragma unroll
    for (int t = 0; t < LIF_T; ++t) {
        m0 = fmaf(beta, m0, xt[t].x);
        m1 = fmaf(beta, m1, xt[t].y);
        m2 = fmaf(beta, m2, xt[t].z);
        m3 = fmaf(beta, m3, xt[t].w);
        float s0 = (m0 >= thresh) ? 1.f : 0.f;
        float s1 = (m1 >= thresh) ? 1.f : 0.f;
        float s2 = (m2 >= thresh) ? 1.f : 0.f;
        float s3 = (m3 >= thresh) ? 1.f : 0.f;
        m0 = (s0 != 0.f) ? 0.f : m0;
        m1 = (s1 != 0.f) ? 0.f : m1;
        m2 = (s2 != 0.f) ? 0.f : m2;
        m3 = (s3 != 0.f) ? 0.f : m3;
        sp[t] = make_float4(s0, s1, s2, s3);
    }

    // Streaming stores: evict-first in L2, don't pollute the x working set.
#pragma unroll
    for (int t = 0; t < LIF_T; ++t) {
        __stcs(&out[(size_t)t * n4 + i], sp[t]);
    }
}

extern "C" void kernel_launch(void* const* d_in, const int* in_sizes, int n_in,
                              void* d_out, int out_size) {
    const float* x = (const float*)d_in[0];
    float* out = (float*)d_out;

    int total = in_sizes[0];
    int N = total / LIF_T;      // 4,194,304
    int n4 = N / 4;             // 1,048,576 float4 columns

    int threads = 256;
    int blocks = (n4 + threads - 1) / threads;  // 4096
    lif_spike_kernel<<<blocks, threads>>>((const float4*)x, (float4*)out, n4);
}